// round 2
// baseline (speedup 1.0000x reference)
#include <cuda_runtime.h>

#define ATT_H 128
#define KVH   256
#define NB    2
#define NS    1024
#define NQ    512

// scratch (no allocations allowed)
__device__ float g_proj_kv[NB*NS*ATT_H];   // (B*S, 128)
__device__ float g_proj_q [NB*NQ*ATT_H];   // (B*SQ, 128)
__device__ float g_E      [NB*NQ*NS];      // unnormalized exp(score)
__device__ float g_part   [4*NB*NQ*KVH];   // split-s partial GEMM results
__device__ float g_inv    [NB*NQ];         // softmax inverse denominators

__device__ __forceinline__ float fast_tanh(float x){ float y; asm("tanh.approx.f32 %0, %1;" : "=f"(y) : "f"(x)); return y; }
__device__ __forceinline__ float fast_ex2 (float x){ float y; asm("ex2.approx.f32 %0, %1;"  : "=f"(y) : "f"(x)); return y; }

// packed dual-FMA: d = a*b + c elementwise on 2 floats (sm_103a FFMA2)
__device__ __forceinline__ float2 ffma2(float2 a, float2 b, float2 c) {
    float2 d;
    asm("fma.rn.f32x2 %0, %1, %2, %3;"
        : "=l"(reinterpret_cast<unsigned long long&>(d))
        : "l"(reinterpret_cast<unsigned long long&>(a)),
          "l"(reinterpret_cast<unsigned long long&>(b)),
          "l"(reinterpret_cast<unsigned long long&>(c)));
    return d;
}

// ---------------- Kernel 1: proj_kv = kv@W_kv+b_kv ; proj_q = q@W_q+b_q ----------------
// 16 rows per block; FFMA2 inner loop (column-paired accumulators).
__global__ void __launch_bounds__(256) proj_kernel(
    const float* __restrict__ kv, const float* __restrict__ qy,
    const float* __restrict__ Wkv, const float* __restrict__ bkv,
    const float* __restrict__ Wq,  const float* __restrict__ bq)
{
    __shared__ float in_sh[16*256];     // 16KB
    __shared__ float w_sh [64*128];     // 32KB (k-chunk of 64)
    const int tid = threadIdx.x;
    const int rb  = blockIdx.x;

    const float *in, *W, *bias; float* out; int row0;
    if (rb < 128) { in = kv; W = Wkv; bias = bkv; out = g_proj_kv; row0 = rb*16; }
    else          { in = qy; W = Wq;  bias = bq;  out = g_proj_q;  row0 = (rb-128)*16; }

    const float4* insrc = (const float4*)(in + row0*256);
    float4* ish4 = (float4*)in_sh;
    #pragma unroll
    for (int i = 0; i < 4; i++) ish4[tid + 256*i] = insrc[tid + 256*i];

    const int a4 = tid & 31;   // float4 column group
    const int rg = tid >> 5;   // 0..7 -> rows rg*2, rg*2+1
    float2 a0xy = make_float2(0.f,0.f), a0zw = make_float2(0.f,0.f);
    float2 a1xy = make_float2(0.f,0.f), a1zw = make_float2(0.f,0.f);

    for (int kc = 0; kc < 4; kc++) {
        __syncthreads();
        const float4* wsrc = (const float4*)(W + kc*64*128);
        float4* wsh4 = (float4*)w_sh;
        #pragma unroll
        for (int i = 0; i < 8; i++) wsh4[tid + 256*i] = wsrc[tid + 256*i];
        __syncthreads();

        const float* i0p = in_sh + (rg*2    )*256 + kc*64;
        const float* i1p = in_sh + (rg*2 + 1)*256 + kc*64;
        #pragma unroll 8
        for (int k = 0; k < 64; k++) {
            float4 w = ((const float4*)w_sh)[k*32 + a4];
            float i0 = i0p[k], i1 = i1p[k];
            float2 i0b = make_float2(i0, i0);
            float2 i1b = make_float2(i1, i1);
            a0xy = ffma2(make_float2(w.x, w.y), i0b, a0xy);
            a0zw = ffma2(make_float2(w.z, w.w), i0b, a0zw);
            a1xy = ffma2(make_float2(w.x, w.y), i1b, a1xy);
            a1zw = ffma2(make_float2(w.z, w.w), i1b, a1zw);
        }
    }
    float4 bb = ((const float4*)bias)[a4];
    float4 o0 = make_float4(a0xy.x + bb.x, a0xy.y + bb.y, a0zw.x + bb.z, a0zw.y + bb.w);
    float4 o1 = make_float4(a1xy.x + bb.x, a1xy.y + bb.y, a1zw.x + bb.z, a1zw.y + bb.w);
    ((float4*)(out + (row0 + rg*2    )*ATT_H))[a4] = o0;
    ((float4*)(out + (row0 + rg*2 + 1)*ATT_H))[a4] = o1;
}

// ---------------- Kernel 2: E[b,q,s] = exp( sum_a w_v[a]*tanh(pk[s,a]+pq[q,a]) + b_v ) ----------------
// Tile: 8 q x 64 s per block. 2048 blocks. MUFU(tanh)-bound (irreducible floor).
__global__ void __launch_bounds__(256) score_kernel(
    const float* __restrict__ wv_g, const float* __restrict__ bv_g)
{
    __shared__ float4 pk_sh[64*33];
    __shared__ float4 pq_sh[8*32];
    __shared__ float4 wv_sh[32];

    const int tid = threadIdx.x;
    const int bid = blockIdx.x;
    const int st  = bid & 15;
    const int qt  = bid >> 4;
    const int b   = qt >> 6;
    const int q0  = (qt & 63) * 8;
    const int s0  = st * 64;

    const float4* pqsrc = (const float4*)(g_proj_q + (b*NQ + q0)*ATT_H);
    pq_sh[tid] = pqsrc[tid];
    if (tid < 32) wv_sh[tid] = ((const float4*)wv_g)[tid];
    const float4* pksrc = (const float4*)(g_proj_kv + (b*NS + s0)*ATT_H);
    #pragma unroll
    for (int i = 0; i < 8; i++) {
        int f4 = tid + 256*i;
        pk_sh[(f4 >> 5)*33 + (f4 & 31)] = pksrc[f4];
    }
    __syncthreads();

    const float bv = __ldg(bv_g);
    const int sl = tid & 63;
    const int qq = tid >> 6;

    float acc0 = 0.f, acc1 = 0.f;
    const float4* pkp  = pk_sh + sl*33;
    const float4* pq0p = pq_sh + (2*qq    )*32;
    const float4* pq1p = pq_sh + (2*qq + 1)*32;

    #pragma unroll 8
    for (int a4 = 0; a4 < 32; a4++) {
        float4 pk = pkp[a4];
        float4 w  = wv_sh[a4];
        float4 p0 = pq0p[a4];
        float4 p1 = pq1p[a4];
        acc0 += w.x * fast_tanh(pk.x + p0.x);
        acc0 += w.y * fast_tanh(pk.y + p0.y);
        acc0 += w.z * fast_tanh(pk.z + p0.z);
        acc0 += w.w * fast_tanh(pk.w + p0.w);
        acc1 += w.x * fast_tanh(pk.x + p1.x);
        acc1 += w.y * fast_tanh(pk.y + p1.y);
        acc1 += w.z * fast_tanh(pk.z + p1.z);
        acc1 += w.w * fast_tanh(pk.w + p1.w);
    }
    float* Eout = g_E + (size_t)(b*NQ + q0 + 2*qq)*NS + s0 + sl;
    Eout[0]  = fast_ex2((acc0 + bv) * 1.44269504f);
    Eout[NS] = fast_ex2((acc1 + bv) * 1.44269504f);
}

// ---------------- Kernel 3: row sums -> g_inv, write normalized attention weights ----------------
// 1024 rows, 1 warp per row, 128 blocks. Deterministic.
__global__ void __launch_bounds__(256) rowsum_kernel(float* __restrict__ out_w)
{
    const int tid  = threadIdx.x;
    const int lane = tid & 31;
    const int row  = blockIdx.x*8 + (tid >> 5);

    const float4* src = (const float4*)(g_E + (size_t)row*NS);
    float4 v[8];
    float s = 0.f;
    #pragma unroll
    for (int i = 0; i < 8; i++) {
        v[i] = src[lane + 32*i];
        s += (v[i].x + v[i].y) + (v[i].z + v[i].w);
    }
    #pragma unroll
    for (int o = 16; o > 0; o >>= 1) s += __shfl_xor_sync(0xffffffffu, s, o);
    const float inv = 1.0f / s;
    if (lane == 0) g_inv[row] = inv;

    float4* dst = (float4*)(out_w + (size_t)row*NS);
    #pragma unroll
    for (int i = 0; i < 8; i++) {
        v[i].x *= inv; v[i].y *= inv; v[i].z *= inv; v[i].w *= inv;
        dst[lane + 32*i] = v[i];
    }
}

// ---------------- Kernel 4: partial output GEMM (raw E), FFMA2, smem-staged kv ----------------
// Block: 16 q x 128 h (hh half) x 256 s (s-chunk). 512 blocks.
__global__ void __launch_bounds__(256) pgemm_kernel(const float* __restrict__ kv)
{
    __shared__ float  E_T[256*17];          // [s][q], stride 17 -> conflict-free transpose
    __shared__ float4 kv_sh[2][16*32];      // double-buffered 16s x 128h chunks (16KB)

    const int tid = threadIdx.x;
    const int bid = blockIdx.x;             // 512 = 64 qt * 2 hh * 4 sc
    const int sc  = bid & 3;
    const int hh  = (bid >> 2) & 1;
    const int qt  = bid >> 3;               // 0..63
    const int b   = qt >> 5;
    const int q0  = (qt & 31) * 16;
    const int s0  = sc * 256;

    // load+transpose E tile: 16 q x 256 s
    const float* Ebase = g_E + ((size_t)(b*NQ + q0))*NS + s0;
    #pragma unroll
    for (int i = 0; i < 4; i++) {
        int f4 = tid + 256*i;               // 0..1023
        int q  = f4 >> 6;
        int s4 = f4 & 63;
        float4 v = ((const float4*)(Ebase + (size_t)q*NS))[s4];
        E_T[(s4*4 + 0)*17 + q] = v.x;
        E_T[(s4*4 + 1)*17 + q] = v.y;
        E_T[(s4*4 + 2)*17 + q] = v.z;
        E_T[(s4*4 + 3)*17 + q] = v.w;
    }

    const float4* kvbase = (const float4*)(kv + ((size_t)b*NS + s0)*KVH + hh*128);
    // stage one 16-s chunk of kv into smem buffer
    #define LOADKV(c, buf)                                                  \
        { _Pragma("unroll")                                                 \
          for (int i = 0; i < 2; i++) {                                     \
              int idx = tid + 256*i;            /* 0..511 */                \
              int ss = idx >> 5, h4i = idx & 31;                            \
              kv_sh[buf][idx] = kvbase[(size_t)((c)*16 + ss)*(KVH/4) + h4i];\
          } }

    LOADKV(0, 0);
    __syncthreads();

    const int h4 = tid & 31;
    const int qg = tid >> 5;                 // 0..7 -> q pair {2qg, 2qg+1}
    float2 a00 = make_float2(0.f,0.f), a01 = make_float2(0.f,0.f);
    float2 a10 = make_float2(0.f,0.f), a11 = make_float2(0.f,0.f);

    for (int c = 0; c < 16; c++) {
        const int cur = c & 1;
        if (c < 15) LOADKV(c + 1, cur ^ 1);
        const float4* kvc = kv_sh[cur];
        const float*  ec  = E_T + (c*16)*17 + qg*2;
        #pragma unroll
        for (int ss = 0; ss < 16; ss++) {
            float4 k4 = kvc[ss*32 + h4];
            float e0 = ec[ss*17], e1 = ec[ss*17 + 1];
            float2 e0b = make_float2(e0, e0);
            float2 e1b = make_float2(e1, e1);
            a00 = ffma2(make_float2(k4.x, k4.y), e0b, a00);
            a01 = ffma2(make_float2(k4.z, k4.w), e0b, a01);
            a10 = ffma2(make_float2(k4.x, k4.y), e1b, a10);
            a11 = ffma2(make_float2(k4.z, k4.w), e1b, a11);
        }
        __syncthreads();
    }

    float* pbase = g_part + ((size_t)sc*NB*NQ + b*NQ + q0 + qg*2)*KVH + hh*128;
    ((float4*)pbase)[h4]         = make_float4(a00.x, a00.y, a01.x, a01.y);
    ((float4*)(pbase + KVH))[h4] = make_float4(a10.x, a10.y, a11.x, a11.y);
    #undef LOADKV
}

// ---------------- Kernel 5: combine partials + normalize ----------------
__global__ void __launch_bounds__(256) combine_kernel(float* __restrict__ out_o)
{
    const int idx = blockIdx.x*256 + threadIdx.x;   // float4 index 0..65535
    const int row = idx >> 6;                       // (b*NQ+q), KVH/4 = 64 f4 per row
    const float inv = g_inv[row];
    float4 s = make_float4(0.f,0.f,0.f,0.f);
    #pragma unroll
    for (int c = 0; c < 4; c++) {
        float4 p = ((const float4*)g_part)[c*(NB*NQ*KVH/4) + idx];
        s.x += p.x; s.y += p.y; s.z += p.z; s.w += p.w;
    }
    s.x *= inv; s.y *= inv; s.z *= inv; s.w *= inv;
    ((float4*)out_o)[idx] = s;
}

extern "C" void kernel_launch(void* const* d_in, const int* in_sizes, int n_in,
                              void* d_out, int out_size)
{
    const float* kv  = (const float*)d_in[0];   // (2,1024,256)
    const float* qy  = (const float*)d_in[1];   // (2,512,256)
    const float* Wkv = (const float*)d_in[2];   // (256,128)
    const float* bkv = (const float*)d_in[3];   // (128)
    const float* Wq  = (const float*)d_in[4];   // (256,128)
    const float* bq  = (const float*)d_in[5];   // (128)
    const float* wv  = (const float*)d_in[6];   // (128)
    const float* bv  = (const float*)d_in[7];   // scalar

    float* out_o = (float*)d_out;               // attention_output: 2*512*256
    float* out_w = out_o + NB*NQ*KVH;           // attention_weight: 2*512*1024

    proj_kernel   <<<192,  256>>>(kv, qy, Wkv, bkv, Wq, bq);
    score_kernel  <<<2048, 256>>>(wv, bv);
    rowsum_kernel <<<128,  256>>>(out_w);
    pgemm_kernel  <<<512,  256>>>(kv);
    combine_kernel<<<256,  256>>>(out_o);
}

// round 3
// speedup vs baseline: 1.2324x; 1.2324x over previous
#include <cuda_runtime.h>

#define ATT_H 128
#define KVH   256
#define NB    2
#define NS    1024
#define NQ    512
#define SK    16      // pgemm k-stage depth

// scratch (no allocations allowed)
__device__ float g_proj_kv[NB*NS*ATT_H];   // (B*S, 128)
__device__ float g_proj_q [NB*NQ*ATT_H];   // (B*SQ, 128)
__device__ float g_E      [NB*NQ*NS];      // unnormalized exp(score)
__device__ float g_part   [8*NB*NQ*KVH];   // split-s partial GEMM results
__device__ float g_inv    [NB*NQ];         // softmax inverse denominators

__device__ __forceinline__ float fast_tanh(float x){ float y; asm("tanh.approx.f32 %0, %1;" : "=f"(y) : "f"(x)); return y; }
__device__ __forceinline__ float fast_ex2 (float x){ float y; asm("ex2.approx.f32 %0, %1;"  : "=f"(y) : "f"(x)); return y; }

// packed dual-FMA: d = a*b + c elementwise on 2 floats (sm_103a FFMA2)
__device__ __forceinline__ float2 ffma2(float2 a, float2 b, float2 c) {
    float2 d;
    asm("fma.rn.f32x2 %0, %1, %2, %3;"
        : "=l"(reinterpret_cast<unsigned long long&>(d))
        : "l"(reinterpret_cast<unsigned long long&>(a)),
          "l"(reinterpret_cast<unsigned long long&>(b)),
          "l"(reinterpret_cast<unsigned long long&>(c)));
    return d;
}

// ---------------- Kernel 1: proj = in@W + b for kv and q rows ----------------
// Block: 32 rows x 64 cols, 128 threads, thread tile 4x4. Grid 192.
__global__ void __launch_bounds__(128) proj_kernel(
    const float* __restrict__ kv, const float* __restrict__ qy,
    const float* __restrict__ Wkv, const float* __restrict__ bkv,
    const float* __restrict__ Wq,  const float* __restrict__ bq)
{
    __shared__ float w_sh [64*64];    // [kk][c] 16KB
    __shared__ float in_T [64*34];    // [kk][row], stride 34 (float2-aligned)

    const int tid = threadIdx.x;
    const int rb  = blockIdx.x;       // 192 = 96 rowblk * 2 colhalf
    const int ch  = rb & 1;
    const int row0g = (rb >> 1) * 32;

    const float *in, *W, *bias; float* out; int rowloc;
    if (row0g < NB*NS) { in = kv; W = Wkv; bias = bkv; out = g_proj_kv; rowloc = row0g; }
    else               { in = qy; W = Wq;  bias = bq;  out = g_proj_q;  rowloc = row0g - NB*NS; }
    in += (size_t)rowloc * 256;

    const int tx = tid & 15;          // col quad: cols ch*64 + tx*4 ..
    const int ty = tid >> 4;          // 0..7 -> rows ty*4 .. ty*4+3

    float2 acc[4][2];
    #pragma unroll
    for (int i = 0; i < 4; i++) { acc[i][0] = make_float2(0.f,0.f); acc[i][1] = make_float2(0.f,0.f); }

    float4 wr[8], ir[4];
    // prefetch chunk 0
    #pragma unroll
    for (int j = 0; j < 8; j++) {
        int f4 = tid + 128*j; int kk = f4 >> 4, c4 = f4 & 15;
        wr[j] = ((const float4*)(W + (size_t)kk*128 + ch*64))[c4];
    }
    #pragma unroll
    for (int j = 0; j < 4; j++) {
        int f4 = tid + 128*j; int r = f4 >> 4, k4 = f4 & 15;
        ir[j] = ((const float4*)(in + (size_t)r*256))[k4];
    }

    for (int kc = 0; kc < 4; kc++) {
        // store staged regs to smem
        #pragma unroll
        for (int j = 0; j < 8; j++) {
            int f4 = tid + 128*j; int kk = f4 >> 4, c4 = f4 & 15;
            ((float4*)w_sh)[kk*16 + c4] = wr[j];
        }
        #pragma unroll
        for (int j = 0; j < 4; j++) {
            int f4 = tid + 128*j; int r = f4 >> 4, k4 = f4 & 15;
            in_T[(k4*4+0)*34 + r] = ir[j].x;
            in_T[(k4*4+1)*34 + r] = ir[j].y;
            in_T[(k4*4+2)*34 + r] = ir[j].z;
            in_T[(k4*4+3)*34 + r] = ir[j].w;
        }
        __syncthreads();
        // prefetch next chunk
        if (kc < 3) {
            #pragma unroll
            for (int j = 0; j < 8; j++) {
                int f4 = tid + 128*j; int kk = f4 >> 4, c4 = f4 & 15;
                wr[j] = ((const float4*)(W + (size_t)((kc+1)*64 + kk)*128 + ch*64))[c4];
            }
            #pragma unroll
            for (int j = 0; j < 4; j++) {
                int f4 = tid + 128*j; int r = f4 >> 4, k4 = f4 & 15;
                ir[j] = ((const float4*)(in + (size_t)r*256 + (kc+1)*64))[k4];
            }
        }
        #pragma unroll 8
        for (int kk = 0; kk < 64; kk++) {
            float4 w4 = ((const float4*)w_sh)[kk*16 + tx];
            float2 i01 = *(const float2*)&in_T[kk*34 + ty*4];
            float2 i23 = *(const float2*)&in_T[kk*34 + ty*4 + 2];
            float iv[4] = {i01.x, i01.y, i23.x, i23.y};
            #pragma unroll
            for (int ri = 0; ri < 4; ri++) {
                float2 ib = make_float2(iv[ri], iv[ri]);
                acc[ri][0] = ffma2(make_float2(w4.x, w4.y), ib, acc[ri][0]);
                acc[ri][1] = ffma2(make_float2(w4.z, w4.w), ib, acc[ri][1]);
            }
        }
        __syncthreads();
    }

    float4 bb = ((const float4*)(bias + ch*64))[tx];
    #pragma unroll
    for (int ri = 0; ri < 4; ri++) {
        float4 o = make_float4(acc[ri][0].x + bb.x, acc[ri][0].y + bb.y,
                               acc[ri][1].x + bb.z, acc[ri][1].y + bb.w);
        *(float4*)(out + (size_t)(rowloc + ty*4 + ri)*ATT_H + ch*64 + tx*4) = o;
    }
}

// ---------------- Kernel 2: E[b,q,s] = exp( sum_a w_v[a]*tanh(pk[s,a]+pq[q,a]) + b_v ) ----------------
// Tile: 8 q x 64 s per block. 2048 blocks. MUFU(tanh)-bound (at ~90% of chip floor).
__global__ void __launch_bounds__(256) score_kernel(
    const float* __restrict__ wv_g, const float* __restrict__ bv_g)
{
    __shared__ float4 pk_sh[64*33];
    __shared__ float4 pq_sh[8*32];
    __shared__ float4 wv_sh[32];

    const int tid = threadIdx.x;
    const int bid = blockIdx.x;
    const int st  = bid & 15;
    const int qt  = bid >> 4;
    const int b   = qt >> 6;
    const int q0  = (qt & 63) * 8;
    const int s0  = st * 64;

    const float4* pqsrc = (const float4*)(g_proj_q + (b*NQ + q0)*ATT_H);
    pq_sh[tid] = pqsrc[tid];
    if (tid < 32) wv_sh[tid] = ((const float4*)wv_g)[tid];
    const float4* pksrc = (const float4*)(g_proj_kv + (b*NS + s0)*ATT_H);
    #pragma unroll
    for (int i = 0; i < 8; i++) {
        int f4 = tid + 256*i;
        pk_sh[(f4 >> 5)*33 + (f4 & 31)] = pksrc[f4];
    }
    __syncthreads();

    const float bv = __ldg(bv_g);
    const int sl = tid & 63;
    const int qq = tid >> 6;

    float acc0 = 0.f, acc1 = 0.f;
    const float4* pkp  = pk_sh + sl*33;
    const float4* pq0p = pq_sh + (2*qq    )*32;
    const float4* pq1p = pq_sh + (2*qq + 1)*32;

    #pragma unroll 8
    for (int a4 = 0; a4 < 32; a4++) {
        float4 pk = pkp[a4];
        float4 w  = wv_sh[a4];
        float4 p0 = pq0p[a4];
        float4 p1 = pq1p[a4];
        acc0 += w.x * fast_tanh(pk.x + p0.x);
        acc0 += w.y * fast_tanh(pk.y + p0.y);
        acc0 += w.z * fast_tanh(pk.z + p0.z);
        acc0 += w.w * fast_tanh(pk.w + p0.w);
        acc1 += w.x * fast_tanh(pk.x + p1.x);
        acc1 += w.y * fast_tanh(pk.y + p1.y);
        acc1 += w.z * fast_tanh(pk.z + p1.z);
        acc1 += w.w * fast_tanh(pk.w + p1.w);
    }
    float* Eout = g_E + (size_t)(b*NQ + q0 + 2*qq)*NS + s0 + sl;
    Eout[0]  = fast_ex2((acc0 + bv) * 1.44269504f);
    Eout[NS] = fast_ex2((acc1 + bv) * 1.44269504f);
}

// ---------------- Kernel 3: row sums -> g_inv, write normalized attention weights ----------------
__global__ void __launch_bounds__(256) rowsum_kernel(float* __restrict__ out_w)
{
    const int tid  = threadIdx.x;
    const int lane = tid & 31;
    const int row  = blockIdx.x*8 + (tid >> 5);

    const float4* src = (const float4*)(g_E + (size_t)row*NS);
    float4 v[8];
    float s = 0.f;
    #pragma unroll
    for (int i = 0; i < 8; i++) {
        v[i] = src[lane + 32*i];
        s += (v[i].x + v[i].y) + (v[i].z + v[i].w);
    }
    #pragma unroll
    for (int o = 16; o > 0; o >>= 1) s += __shfl_xor_sync(0xffffffffu, s, o);
    const float inv = 1.0f / s;
    if (lane == 0) g_inv[row] = inv;

    float4* dst = (float4*)(out_w + (size_t)row*NS);
    #pragma unroll
    for (int i = 0; i < 8; i++) {
        v[i].x *= inv; v[i].y *= inv; v[i].z *= inv; v[i].w *= inv;
        dst[lane + 32*i] = v[i];
    }
}

// ---------------- Kernel 4: partial output GEMM, 128q x 128h x 128s blocks ----------------
// 256 threads, 8x8 thread tile -> FMA-bound. Grid 128 (split-K over 8 s-chunks).
__global__ void __launch_bounds__(256) pgemm_kernel(const float* __restrict__ kv)
{
    __shared__ float kvs[2][SK*128];   // [k][h]
    __shared__ float Es [2][SK*128];   // [k][q] (transposed on store)

    const int tid = threadIdx.x;
    const int bid = blockIdx.x;        // 128 = 8 qt * 2 hh * 8 sc
    const int sc  = bid & 7;
    const int hh  = (bid >> 3) & 1;
    const int qt  = bid >> 4;          // 0..7 over flattened b*NQ+q space
    const int row0 = qt * 128;
    const int b   = qt >> 2;
    const int s0  = sc * 128;

    const int tx = tid & 15;           // h octet: h = tx*8..tx*8+7
    const int ty = tid >> 4;           // q octet: q = ty*8..ty*8+7

    const float* kvg = kv  + ((size_t)b*NS + s0)*KVH + hh*128;
    const float* Eg  = g_E + (size_t)row0*NS + s0;

    float4 rk[2], re[2];
    #define LOADG(c)                                                         \
        { _Pragma("unroll")                                                  \
          for (int j = 0; j < 2; j++) {                                      \
              int f4 = tid + 256*j;                                          \
              int k = f4 >> 5, h4 = f4 & 31;                                 \
              rk[j] = *(const float4*)(kvg + (size_t)((c)*SK + k)*KVH + h4*4); } \
          _Pragma("unroll")                                                  \
          for (int j = 0; j < 2; j++) {                                      \
              int f4 = tid + 256*j;                                          \
              int q = f4 >> 2, s4 = f4 & 3;                                  \
              re[j] = *(const float4*)(Eg + (size_t)q*NS + (c)*SK + s4*4); } }

    #define STORES(buf)                                                      \
        { _Pragma("unroll")                                                  \
          for (int j = 0; j < 2; j++) {                                      \
              int f4 = tid + 256*j;                                          \
              int k = f4 >> 5, h4 = f4 & 31;                                 \
              ((float4*)(kvs[buf] + k*128))[h4] = rk[j]; }                   \
          _Pragma("unroll")                                                  \
          for (int j = 0; j < 2; j++) {                                      \
              int f4 = tid + 256*j;                                          \
              int q = f4 >> 2, s4 = f4 & 3;                                  \
              Es[buf][(s4*4+0)*128 + q] = re[j].x;                           \
              Es[buf][(s4*4+1)*128 + q] = re[j].y;                           \
              Es[buf][(s4*4+2)*128 + q] = re[j].z;                           \
              Es[buf][(s4*4+3)*128 + q] = re[j].w; } }

    LOADG(0);
    STORES(0);
    __syncthreads();

    float2 acc[8][4];
    #pragma unroll
    for (int i = 0; i < 8; i++)
        #pragma unroll
        for (int j = 0; j < 4; j++) acc[i][j] = make_float2(0.f, 0.f);

    for (int c = 0; c < 8; c++) {
        const int buf = c & 1;
        if (c < 7) LOADG(c+1);
        #pragma unroll
        for (int k = 0; k < SK; k++) {
            float4 kv0 = ((const float4*)(kvs[buf] + k*128))[tx*2];
            float4 kv1 = ((const float4*)(kvs[buf] + k*128))[tx*2 + 1];
            float4 e0  = ((const float4*)(Es[buf]  + k*128))[ty*2];
            float4 e1  = ((const float4*)(Es[buf]  + k*128))[ty*2 + 1];
            float2 kp[4] = { make_float2(kv0.x, kv0.y), make_float2(kv0.z, kv0.w),
                             make_float2(kv1.x, kv1.y), make_float2(kv1.z, kv1.w) };
            float ev[8] = { e0.x, e0.y, e0.z, e0.w, e1.x, e1.y, e1.z, e1.w };
            #pragma unroll
            for (int qi = 0; qi < 8; qi++) {
                float2 eb = make_float2(ev[qi], ev[qi]);
                #pragma unroll
                for (int hj = 0; hj < 4; hj++)
                    acc[qi][hj] = ffma2(kp[hj], eb, acc[qi][hj]);
            }
        }
        __syncthreads();
        if (c < 7) { STORES(buf ^ 1); __syncthreads(); }
    }

    float* pb = g_part + ((size_t)sc*(NB*NQ) + row0 + ty*8)*KVH + hh*128 + tx*8;
    #pragma unroll
    for (int qi = 0; qi < 8; qi++) {
        *(float4*)(pb + (size_t)qi*KVH)     = make_float4(acc[qi][0].x, acc[qi][0].y, acc[qi][1].x, acc[qi][1].y);
        *(float4*)(pb + (size_t)qi*KVH + 4) = make_float4(acc[qi][2].x, acc[qi][2].y, acc[qi][3].x, acc[qi][3].y);
    }
    #undef LOADG
    #undef STORES
}

// ---------------- Kernel 5: combine 8 partials + normalize ----------------
__global__ void __launch_bounds__(256) combine_kernel(float* __restrict__ out_o)
{
    const int idx = blockIdx.x*256 + threadIdx.x;   // float4 index 0..65535
    const int row = idx >> 6;                       // (b*NQ+q)
    const float inv = g_inv[row];
    float4 s = make_float4(0.f,0.f,0.f,0.f);
    #pragma unroll
    for (int c = 0; c < 8; c++) {
        float4 p = ((const float4*)g_part)[(size_t)c*(NB*NQ*KVH/4) + idx];
        s.x += p.x; s.y += p.y; s.z += p.z; s.w += p.w;
    }
    s.x *= inv; s.y *= inv; s.z *= inv; s.w *= inv;
    ((float4*)out_o)[idx] = s;
}

extern "C" void kernel_launch(void* const* d_in, const int* in_sizes, int n_in,
                              void* d_out, int out_size)
{
    const float* kv  = (const float*)d_in[0];   // (2,1024,256)
    const float* qy  = (const float*)d_in[1];   // (2,512,256)
    const float* Wkv = (const float*)d_in[2];   // (256,128)
    const float* bkv = (const float*)d_in[3];   // (128)
    const float* Wq  = (const float*)d_in[4];   // (256,128)
    const float* bq  = (const float*)d_in[5];   // (128)
    const float* wv  = (const float*)d_in[6];   // (128)
    const float* bv  = (const float*)d_in[7];   // scalar

    float* out_o = (float*)d_out;               // attention_output: 2*512*256
    float* out_w = out_o + NB*NQ*KVH;           // attention_weight: 2*512*1024

    proj_kernel   <<<192,  128>>>(kv, qy, Wkv, bkv, Wq, bq);
    score_kernel  <<<2048, 256>>>(wv, bv);
    rowsum_kernel <<<128,  256>>>(out_w);
    pgemm_kernel  <<<128,  256>>>(kv);
    combine_kernel<<<256,  256>>>(out_o);
}

// round 4
// speedup vs baseline: 1.3136x; 1.0659x over previous
#include <cuda_runtime.h>

#define ATT_H 128
#define KVH   256
#define NB    2
#define NS    1024
#define NQ    512
#define SK    16      // pgemm k-stage depth
#define NROWS (NB*NS + NB*NQ)   // 3072 projection rows

// scratch (no allocations allowed)
__device__ float g_proj_kv[NB*NS*ATT_H];   // (B*S, 128)
__device__ float g_proj_q [NB*NQ*ATT_H];   // (B*SQ, 128)
__device__ float g_pp     [2*NROWS*ATT_H]; // proj k-split partials
__device__ float g_E      [NB*NQ*NS];      // unnormalized exp(score)
__device__ float g_part   [8*NB*NQ*KVH];   // split-s partial GEMM results
__device__ float g_inv    [NB*NQ];         // softmax inverse denominators

__device__ __forceinline__ float fast_tanh(float x){ float y; asm("tanh.approx.f32 %0, %1;" : "=f"(y) : "f"(x)); return y; }
__device__ __forceinline__ float fast_ex2 (float x){ float y; asm("ex2.approx.f32 %0, %1;"  : "=f"(y) : "f"(x)); return y; }

// packed dual-FMA (sm_103a FFMA2)
__device__ __forceinline__ float2 ffma2(float2 a, float2 b, float2 c) {
    float2 d;
    asm("fma.rn.f32x2 %0, %1, %2, %3;"
        : "=l"(reinterpret_cast<unsigned long long&>(d))
        : "l"(reinterpret_cast<unsigned long long&>(a)),
          "l"(reinterpret_cast<unsigned long long&>(b)),
          "l"(reinterpret_cast<unsigned long long&>(c)));
    return d;
}

__device__ __forceinline__ void cp16(void* dst, const void* src) {
    unsigned d = (unsigned)__cvta_generic_to_shared(dst);
    asm volatile("cp.async.cg.shared.global [%0], [%1], 16;" :: "r"(d), "l"(src));
}
__device__ __forceinline__ void cp_commit() { asm volatile("cp.async.commit_group;"); }
__device__ __forceinline__ void cp_wait0()  { asm volatile("cp.async.wait_group 0;"); }

// ---------------- Kernel 1: proj partials, k-split x2 ----------------
// Block: 32 rows x 64 cols x 128 k, 128 threads, thread tile 4x4. Grid 384.
__global__ void __launch_bounds__(128) proj_kernel(
    const float* __restrict__ kv, const float* __restrict__ qy,
    const float* __restrict__ Wkv, const float* __restrict__ Wq)
{
    __shared__ float w_sh [64*64];    // [kk][c] 16KB
    __shared__ float in_T [64*34];    // [kk][row]

    const int tid = threadIdx.x;
    const int rb  = blockIdx.x;       // 384 = 96 rowblk * 2 colhalf * 2 khalf
    const int kh  = rb & 1;
    const int ch  = (rb >> 1) & 1;
    const int row0g = (rb >> 2) * 32;

    const float *in, *W;
    if (row0g < NB*NS) { in = kv + (size_t)row0g*256;          W = Wkv; }
    else               { in = qy + (size_t)(row0g - NB*NS)*256; W = Wq;  }
    in += kh*128;
    W  += (size_t)kh*128*128;

    const int tx = tid & 15;          // col quad
    const int ty = tid >> 4;          // 0..7 -> rows ty*4..+3

    float2 acc[4][2];
    #pragma unroll
    for (int i = 0; i < 4; i++) { acc[i][0] = make_float2(0.f,0.f); acc[i][1] = make_float2(0.f,0.f); }

    float4 wr[8], ir[4];
    #pragma unroll
    for (int j = 0; j < 8; j++) {
        int f4 = tid + 128*j; int kk = f4 >> 4, c4 = f4 & 15;
        wr[j] = *(const float4*)(W + (size_t)kk*128 + ch*64 + c4*4);
    }
    #pragma unroll
    for (int j = 0; j < 4; j++) {
        int f4 = tid + 128*j; int r = f4 >> 4, k4 = f4 & 15;
        ir[j] = *(const float4*)(in + (size_t)r*256 + k4*4);
    }

    for (int kc = 0; kc < 2; kc++) {
        #pragma unroll
        for (int j = 0; j < 8; j++) {
            int f4 = tid + 128*j; int kk = f4 >> 4, c4 = f4 & 15;
            ((float4*)w_sh)[kk*16 + c4] = wr[j];
        }
        #pragma unroll
        for (int j = 0; j < 4; j++) {
            int f4 = tid + 128*j; int r = f4 >> 4, k4 = f4 & 15;
            in_T[(k4*4+0)*34 + r] = ir[j].x;
            in_T[(k4*4+1)*34 + r] = ir[j].y;
            in_T[(k4*4+2)*34 + r] = ir[j].z;
            in_T[(k4*4+3)*34 + r] = ir[j].w;
        }
        __syncthreads();
        if (kc < 1) {
            #pragma unroll
            for (int j = 0; j < 8; j++) {
                int f4 = tid + 128*j; int kk = f4 >> 4, c4 = f4 & 15;
                wr[j] = *(const float4*)(W + (size_t)(64 + kk)*128 + ch*64 + c4*4);
            }
            #pragma unroll
            for (int j = 0; j < 4; j++) {
                int f4 = tid + 128*j; int r = f4 >> 4, k4 = f4 & 15;
                ir[j] = *(const float4*)(in + (size_t)r*256 + 64 + k4*4);
            }
        }
        #pragma unroll 8
        for (int kk = 0; kk < 64; kk++) {
            float4 w4 = ((const float4*)w_sh)[kk*16 + tx];
            float2 i01 = *(const float2*)&in_T[kk*34 + ty*4];
            float2 i23 = *(const float2*)&in_T[kk*34 + ty*4 + 2];
            float iv[4] = {i01.x, i01.y, i23.x, i23.y};
            #pragma unroll
            for (int ri = 0; ri < 4; ri++) {
                float2 ib = make_float2(iv[ri], iv[ri]);
                acc[ri][0] = ffma2(make_float2(w4.x, w4.y), ib, acc[ri][0]);
                acc[ri][1] = ffma2(make_float2(w4.z, w4.w), ib, acc[ri][1]);
            }
        }
        __syncthreads();
    }

    float* outp = g_pp + (size_t)kh*NROWS*ATT_H + (size_t)(row0g + ty*4)*ATT_H + ch*64 + tx*4;
    #pragma unroll
    for (int ri = 0; ri < 4; ri++)
        *(float4*)(outp + (size_t)ri*ATT_H) =
            make_float4(acc[ri][0].x, acc[ri][0].y, acc[ri][1].x, acc[ri][1].y);
}

// ---------------- Kernel 1b: combine proj k-halves + bias ----------------
__global__ void __launch_bounds__(256) proj_fix_kernel(
    const float* __restrict__ bkv, const float* __restrict__ bq)
{
    const int idx = blockIdx.x*256 + threadIdx.x;   // f4 index, 98304 total
    const int row = idx >> 5;
    const int c4  = idx & 31;
    float4 a = ((const float4*)g_pp)[idx];
    float4 b = ((const float4*)g_pp)[idx + NROWS*32];
    const float* bias; float* out; int rloc;
    if (row < NB*NS) { bias = bkv; out = g_proj_kv; rloc = row; }
    else             { bias = bq;  out = g_proj_q;  rloc = row - NB*NS; }
    float4 bb = ((const float4*)bias)[c4];
    float4 o = make_float4(a.x+b.x+bb.x, a.y+b.y+bb.y, a.z+b.z+bb.z, a.w+b.w+bb.w);
    ((float4*)(out + (size_t)rloc*ATT_H))[c4] = o;
}

// ---------------- Kernel 2: E[b,q,s] = exp( sum_a w_v[a]*tanh(pk[s,a]+pq[q,a]) + b_v ) ----------------
// Tile: 8 q x 64 s per block. 2048 blocks. MUFU(tanh)-bound (chip floor).
__global__ void __launch_bounds__(256) score_kernel(
    const float* __restrict__ wv_g, const float* __restrict__ bv_g)
{
    __shared__ float4 pk_sh[64*33];
    __shared__ float4 pq_sh[8*32];
    __shared__ float4 wv_sh[32];

    const int tid = threadIdx.x;
    const int bid = blockIdx.x;
    const int st  = bid & 15;
    const int qt  = bid >> 4;
    const int b   = qt >> 6;
    const int q0  = (qt & 63) * 8;
    const int s0  = st * 64;

    const float4* pqsrc = (const float4*)(g_proj_q + (b*NQ + q0)*ATT_H);
    pq_sh[tid] = pqsrc[tid];
    if (tid < 32) wv_sh[tid] = ((const float4*)wv_g)[tid];
    const float4* pksrc = (const float4*)(g_proj_kv + (b*NS + s0)*ATT_H);
    #pragma unroll
    for (int i = 0; i < 8; i++) {
        int f4 = tid + 256*i;
        pk_sh[(f4 >> 5)*33 + (f4 & 31)] = pksrc[f4];
    }
    __syncthreads();

    const float bv = __ldg(bv_g);
    const int sl = tid & 63;
    const int qq = tid >> 6;

    float acc0 = 0.f, acc1 = 0.f;
    const float4* pkp  = pk_sh + sl*33;
    const float4* pq0p = pq_sh + (2*qq    )*32;
    const float4* pq1p = pq_sh + (2*qq + 1)*32;

    #pragma unroll 8
    for (int a4 = 0; a4 < 32; a4++) {
        float4 pk = pkp[a4];
        float4 w  = wv_sh[a4];
        float4 p0 = pq0p[a4];
        float4 p1 = pq1p[a4];
        acc0 += w.x * fast_tanh(pk.x + p0.x);
        acc0 += w.y * fast_tanh(pk.y + p0.y);
        acc0 += w.z * fast_tanh(pk.z + p0.z);
        acc0 += w.w * fast_tanh(pk.w + p0.w);
        acc1 += w.x * fast_tanh(pk.x + p1.x);
        acc1 += w.y * fast_tanh(pk.y + p1.y);
        acc1 += w.z * fast_tanh(pk.z + p1.z);
        acc1 += w.w * fast_tanh(pk.w + p1.w);
    }
    float* Eout = g_E + (size_t)(b*NQ + q0 + 2*qq)*NS + s0 + sl;
    Eout[0]  = fast_ex2((acc0 + bv) * 1.44269504f);
    Eout[NS] = fast_ex2((acc1 + bv) * 1.44269504f);
}

// ---------------- Kernel 3: row sums -> g_inv, write normalized attention weights ----------------
__global__ void __launch_bounds__(256) rowsum_kernel(float* __restrict__ out_w)
{
    const int tid  = threadIdx.x;
    const int lane = tid & 31;
    const int row  = blockIdx.x*8 + (tid >> 5);

    const float4* src = (const float4*)(g_E + (size_t)row*NS);
    float4 v[8];
    float s = 0.f;
    #pragma unroll
    for (int i = 0; i < 8; i++) {
        v[i] = src[lane + 32*i];
        s += (v[i].x + v[i].y) + (v[i].z + v[i].w);
    }
    #pragma unroll
    for (int o = 16; o > 0; o >>= 1) s += __shfl_xor_sync(0xffffffffu, s, o);
    const float inv = 1.0f / s;
    if (lane == 0) g_inv[row] = inv;

    float4* dst = (float4*)(out_w + (size_t)row*NS);
    #pragma unroll
    for (int i = 0; i < 8; i++) {
        v[i].x *= inv; v[i].y *= inv; v[i].z *= inv; v[i].w *= inv;
        dst[lane + 32*i] = v[i];
    }
}

// ---------------- Kernel 4: partial output GEMM, 128q x 128h x 128s blocks ----------------
// 512 threads, 8q x 4h thread tile, cp.async kv staging. Grid 128.
__global__ void __launch_bounds__(512) pgemm_kernel(const float* __restrict__ kv)
{
    __shared__ float kvs[2][SK*128];   // [k][h] 16KB
    __shared__ float Es [2][SK*132];   // [k][q] padded: 2-way max conflict on transpose

    const int tid = threadIdx.x;
    const int bid = blockIdx.x;        // 128 = 8 qt * 2 hh * 8 sc
    const int sc  = bid & 7;
    const int hh  = (bid >> 3) & 1;
    const int qt  = bid >> 4;
    const int row0 = qt * 128;
    const int b   = qt >> 2;
    const int s0  = sc * 128;

    const int tx = tid & 31;           // h quad: h = tx*4..tx*4+3
    const int ty = tid >> 5;           // 0..15 -> q octet ty*8..+7

    const float* kvg = kv  + ((size_t)b*NS + s0)*KVH + hh*128;
    const float* Eg  = g_E + (size_t)row0*NS + s0;

    const int lk  = tid >> 5;          // load: k row (0..15)
    const int lh4 = tid & 31;          // load: h quad
    const int lq  = tid >> 2;          // load: E q row (0..127)
    const int ls4 = tid & 3;           // load: E s quad

    float4 re;
    #define LOADKV(c, buf) \
        cp16(&kvs[buf][lk*128 + lh4*4], kvg + (size_t)((c)*SK + lk)*KVH + lh4*4); cp_commit();
    #define LOADE(c) \
        re = *(const float4*)(Eg + (size_t)lq*NS + (c)*SK + ls4*4);
    #define STORE_E(buf) \
        { Es[buf][(ls4*4+0)*132 + lq] = re.x; \
          Es[buf][(ls4*4+1)*132 + lq] = re.y; \
          Es[buf][(ls4*4+2)*132 + lq] = re.z; \
          Es[buf][(ls4*4+3)*132 + lq] = re.w; }

    LOADKV(0, 0);
    LOADE(0);
    STORE_E(0);
    cp_wait0();
    __syncthreads();

    float2 acc[8][2];
    #pragma unroll
    for (int i = 0; i < 8; i++) { acc[i][0] = make_float2(0.f,0.f); acc[i][1] = make_float2(0.f,0.f); }

    for (int c = 0; c < 8; c++) {
        const int buf = c & 1;
        if (c < 7) { LOADKV(c+1, buf^1); LOADE(c+1); }
        #pragma unroll
        for (int k = 0; k < SK; k++) {
            float4 k4 = ((const float4*)(kvs[buf] + k*128))[tx];
            float4 e0 = ((const float4*)(Es[buf]  + k*132))[ty*2];
            float4 e1 = ((const float4*)(Es[buf]  + k*132))[ty*2 + 1];
            float2 kp0 = make_float2(k4.x, k4.y);
            float2 kp1 = make_float2(k4.z, k4.w);
            float ev[8] = { e0.x, e0.y, e0.z, e0.w, e1.x, e1.y, e1.z, e1.w };
            #pragma unroll
            for (int qi = 0; qi < 8; qi++) {
                float2 eb = make_float2(ev[qi], ev[qi]);
                acc[qi][0] = ffma2(kp0, eb, acc[qi][0]);
                acc[qi][1] = ffma2(kp1, eb, acc[qi][1]);
            }
        }
        if (c < 7) { STORE_E(buf^1); cp_wait0(); }
        __syncthreads();
    }

    float* pb = g_part + ((size_t)sc*(NB*NQ) + row0 + ty*8)*KVH + hh*128 + tx*4;
    #pragma unroll
    for (int qi = 0; qi < 8; qi++)
        *(float4*)(pb + (size_t)qi*KVH) =
            make_float4(acc[qi][0].x, acc[qi][0].y, acc[qi][1].x, acc[qi][1].y);
    #undef LOADKV
    #undef LOADE
    #undef STORE_E
}

// ---------------- Kernel 5: combine 8 partials + normalize ----------------
__global__ void __launch_bounds__(256) combine_kernel(float* __restrict__ out_o)
{
    const int idx = blockIdx.x*256 + threadIdx.x;   // float4 index 0..65535
    const int row = idx >> 6;                       // (b*NQ+q)
    const float inv = g_inv[row];
    float4 s = make_float4(0.f,0.f,0.f,0.f);
    #pragma unroll
    for (int c = 0; c < 8; c++) {
        float4 p = ((const float4*)g_part)[(size_t)c*(NB*NQ*KVH/4) + idx];
        s.x += p.x; s.y += p.y; s.z += p.z; s.w += p.w;
    }
    s.x *= inv; s.y *= inv; s.z *= inv; s.w *= inv;
    ((float4*)out_o)[idx] = s;
}

extern "C" void kernel_launch(void* const* d_in, const int* in_sizes, int n_in,
                              void* d_out, int out_size)
{
    const float* kv  = (const float*)d_in[0];   // (2,1024,256)
    const float* qy  = (const float*)d_in[1];   // (2,512,256)
    const float* Wkv = (const float*)d_in[2];   // (256,128)
    const float* bkv = (const float*)d_in[3];   // (128)
    const float* Wq  = (const float*)d_in[4];   // (256,128)
    const float* bq  = (const float*)d_in[5];   // (128)
    const float* wv  = (const float*)d_in[6];   // (128)
    const float* bv  = (const float*)d_in[7];   // scalar

    float* out_o = (float*)d_out;               // attention_output: 2*512*256
    float* out_w = out_o + NB*NQ*KVH;           // attention_weight: 2*512*1024

    proj_kernel   <<<384,  128>>>(kv, qy, Wkv, Wq);
    proj_fix_kernel<<<384, 256>>>(bkv, bq);
    score_kernel  <<<2048, 256>>>(wv, bv);
    rowsum_kernel <<<128,  256>>>(out_w);
    pgemm_kernel  <<<128,  512>>>(kv);
    combine_kernel<<<256,  256>>>(out_o);
}